// round 1
// baseline (speedup 1.0000x reference)
#include <cuda_runtime.h>

// Problem constants
//  H=8, KB=8 cells; OB=64, IB=64, K=9, L=9; ZD=64, PD=16, DH=128
//  out: [512, 512, 9, 9] fp32 = 21,233,664 elements

__device__ float g_hid[64 * 128];   // relu(x @ W1^T + b1), scratch between kernels

// ---------------------------------------------------------------------------
// Kernel 1: hid[r][j] = relu(b1[j] + sum_t x[r][t] * W1[j][t]),  x = [z_all[r], pde]
// grid 64 (r), block 128 (j)
// ---------------------------------------------------------------------------
__global__ __launch_bounds__(128)
void hypernet_hid(const float* __restrict__ z_all,
                  const float* __restrict__ W1,
                  const float* __restrict__ b1,
                  const float* __restrict__ pde)
{
    __shared__ float xs[80];
    const int r = blockIdx.x;
    const int j = threadIdx.x;
    if (j < 64)       xs[j] = z_all[r * 64 + j];
    else if (j < 80)  xs[j] = pde[j - 64];
    __syncthreads();

    const float4* wp = (const float4*)(W1 + j * 80);   // 320B row, 16B aligned
    float acc = b1[j];
#pragma unroll
    for (int t = 0; t < 20; ++t) {
        float4 w = wp[t];
        acc = fmaf(w.x, xs[4*t+0], acc);
        acc = fmaf(w.y, xs[4*t+1], acc);
        acc = fmaf(w.z, xs[4*t+2], acc);
        acc = fmaf(w.w, xs[4*t+3], acc);
    }
    g_hid[r * 128 + j] = fmaxf(acc, 0.0f);
}

// ---------------------------------------------------------------------------
// Kernel 2 (fused): exe = hid @ W2^T + b2 ; out[o,i,k,l] = exe * unet[o,i,l]
//
// grid 512: blockIdx.x = ob*8 + ibg   (ob in [0,64), ibg in [0,8), ibbase=8*ibg)
// block 128 threads: tid = cg*8 + ibl (cg in [0,16) -> 4 cells each; ibl in [0,8))
// Per block: 72 contiguous W2 rows [base9, base9+72), all 64 cells.
// GEMM register tile: 4 cells x 9 k per thread, K=128 split in two d-halves.
// smem (static, 36,992 B -> 6 blocks/SM, all 512 blocks resident):
//   GEMM phase: hs[64][68] at 0, w2s[72][68] at 4352
//   epilogue:   exe_s[64][72] at 0 (alias), un_s[64][72] at 4608 (alias)
// ---------------------------------------------------------------------------
__global__ __launch_bounds__(128, 6)
void fused_weight_gen(const float* __restrict__ W2,
                      const float* __restrict__ b2,
                      const float* __restrict__ unet,
                      float* __restrict__ out)
{
    __shared__ float sm[9248];
    float* hs    = sm;            // [64][68]
    float* w2s   = sm + 4352;     // [72][68]
    float* exe_s = sm;            // [64][72] (alias, used after GEMM)
    float* un_s  = sm + 4608;     // [64][72] (alias, used after GEMM)

    const int tid    = threadIdx.x;
    const int ob     = blockIdx.x >> 3;
    const int ibg    = blockIdx.x & 7;
    const int ibbase = ibg * 8;
    const int base9  = (ob * 64 + ibbase) * 9;   // first of 72 contiguous W2 rows

    const int cg  = tid >> 3;   // cell group: cells cg*4 .. cg*4+3
    const int ibl = tid & 7;    // local ib:   kk = ibl*9 + k

    float acc[4][9];
#pragma unroll
    for (int j = 0; j < 4; ++j)
#pragma unroll
        for (int k = 0; k < 9; ++k) acc[j][k] = 0.0f;

    // ---- K loop in two halves of 64 (keeps smem at 37KB) ----
#pragma unroll 1
    for (int phase = 0; phase < 2; ++phase) {
        const int dbase = phase * 64;

        // hid half: 64 cells x 16 float4
        for (int idx = tid; idx < 1024; idx += 128) {
            int cell = idx >> 4, q = idx & 15;
            float4 v = *(const float4*)(g_hid + cell * 128 + dbase + 4 * q);
            *(float4*)(hs + cell * 68 + 4 * q) = v;
        }
        // W2 half: 72 rows x 16 float4 (rows contiguous in global)
        for (int idx = tid; idx < 1152; idx += 128) {
            int row = idx >> 4, q = idx & 15;
            float4 v = *(const float4*)(W2 + (size_t)(base9 + row) * 128 + dbase + 4 * q);
            *(float4*)(w2s + row * 68 + 4 * q) = v;
        }
        __syncthreads();

        const float* hp = hs + cg * 4 * 68;
        const float* wp = w2s + ibl * 9 * 68;
#pragma unroll 8
        for (int d = 0; d < 64; ++d) {
            float h0 = hp[d];
            float h1 = hp[68 + d];
            float h2 = hp[136 + d];
            float h3 = hp[204 + d];
#pragma unroll
            for (int k = 0; k < 9; ++k) {
                float w = wp[k * 68 + d];
                acc[0][k] = fmaf(h0, w, acc[0][k]);
                acc[1][k] = fmaf(h1, w, acc[1][k]);
                acc[2][k] = fmaf(h2, w, acc[2][k]);
                acc[3][k] = fmaf(h3, w, acc[3][k]);
            }
        }
        __syncthreads();   // done reading this half before smem is reused
    }

    // ---- finalize exe into smem (aliases hs/w2s; synced above) ----
    float bv[9];
#pragma unroll
    for (int k = 0; k < 9; ++k) bv[k] = b2[base9 + ibl * 9 + k];
#pragma unroll
    for (int j = 0; j < 4; ++j) {
        int cell = cg * 4 + j;
#pragma unroll
        for (int k = 0; k < 9; ++k)
            exe_s[cell * 72 + ibl * 9 + k] = acc[j][k] + bv[k];
    }

    // stage unet: per cell 72 contiguous floats = 18 float4
    for (int idx = tid; idx < 1152; idx += 128) {
        int cell = idx / 18, q = idx - cell * 18;
        int h = cell >> 3, kb = cell & 7;
        size_t bu = ((size_t)(h * 64 + ob) * 512 + (size_t)(kb * 64 + ibbase)) * 9;
        float4 v = *(const float4*)(unet + bu + 4 * q);
        *(float4*)(un_s + cell * 72 + 4 * q) = v;
    }
    __syncthreads();

    // ---- epilogue: per cell a contiguous 648-float chunk (8 ib x 81), float4 writes ----
    // chunk element e = ibl*81 + k*9 + l ;  e/9 = kk = ibl*9+k ;  un idx = (e/81)*9 + e%9
    for (int idx = tid; idx < 10368; idx += 128) {
        int cell = idx / 162;
        int r    = idx - cell * 162;
        int e    = r * 4;
        int h = cell >> 3, kb = cell & 7;
        size_t obase = ((size_t)(h * 64 + ob) * 512 + (size_t)(kb * 64 + ibbase)) * 81;
        float v[4];
#pragma unroll
        for (int t = 0; t < 4; ++t) {
            int et  = e + t;
            int kk  = et / 9;
            int ib2 = et / 81;
            int l   = et - kk * 9;
            v[t] = exe_s[cell * 72 + kk] * un_s[cell * 72 + ib2 * 9 + l];
        }
        *(float4*)(out + obase + e) = make_float4(v[0], v[1], v[2], v[3]);
    }
}

// ---------------------------------------------------------------------------
extern "C" void kernel_launch(void* const* d_in, const int* in_sizes, int n_in,
                              void* d_out, int out_size)
{
    const float* z_all = (const float*)d_in[0];   // [64, 64]
    const float* W1    = (const float*)d_in[1];   // [128, 80]
    const float* b1    = (const float*)d_in[2];   // [128]
    const float* W2    = (const float*)d_in[3];   // [36864, 128]
    const float* b2    = (const float*)d_in[4];   // [36864]
    const float* unet  = (const float*)d_in[5];   // [512, 512, 9]
    const float* pde   = (const float*)d_in[6];   // [16]
    float* out = (float*)d_out;                   // [512, 512, 9, 9]

    hypernet_hid<<<64, 128>>>(z_all, W1, b1, pde);
    fused_weight_gen<<<512, 128>>>(W2, b2, unet, out);
}

// round 3
// speedup vs baseline: 1.1062x; 1.1062x over previous
#include <cuda_runtime.h>
#include <cstdint>

// Problem constants
//  H=8, KB=8 cells; OB=64, IB=64, K=9, L=9; ZD=64, PD=16, DH=128
//  out: [512, 512, 9, 9] fp32 = 21,233,664 elements

__device__ float g_hid[64 * 128];   // relu(x @ W1^T + b1), scratch between kernels

// Packed f32x2 FMA (sm_103a): d = a*b + c elementwise on two fp32 lanes.
#define FMA_F32X2(d, a, b, c) \
    asm("fma.rn.f32x2 %0, %1, %2, %3;" : "=l"(d) : "l"(a), "l"(b), "l"(c))

// ---------------------------------------------------------------------------
// Kernel 1: hid[r][j] = relu(b1[j] + sum_t x[r][t] * W1[j][t]),  x = [z_all[r], pde]
// ---------------------------------------------------------------------------
__global__ __launch_bounds__(128)
void hypernet_hid(const float* __restrict__ z_all,
                  const float* __restrict__ W1,
                  const float* __restrict__ b1,
                  const float* __restrict__ pde)
{
    __shared__ float xs[80];
    const int r = blockIdx.x;
    const int j = threadIdx.x;
    if (j < 64)       xs[j] = z_all[r * 64 + j];
    else if (j < 80)  xs[j] = pde[j - 64];
    __syncthreads();

    const float4* wp = (const float4*)(W1 + j * 80);
    float acc = b1[j];
#pragma unroll
    for (int t = 0; t < 20; ++t) {
        float4 w = wp[t];
        acc = fmaf(w.x, xs[4*t+0], acc);
        acc = fmaf(w.y, xs[4*t+1], acc);
        acc = fmaf(w.z, xs[4*t+2], acc);
        acc = fmaf(w.w, xs[4*t+3], acc);
    }
    g_hid[r * 128 + j] = fmaxf(acc, 0.0f);
}

// ---------------------------------------------------------------------------
// Kernel 2 (fused): exe = hid @ W2^T + b2 ; out[o,i,k,l] = exe * unet[o,i,l]
//
// grid 512: blockIdx.x = ob*8 + ibg   (ob in [0,64), ibg in [0,8))
// block 256 threads: tid = cg*8 + ibl (cg in [0,32) -> 2 cells; ibl in [0,8) -> 9 cols)
// GEMM: f32x2 accumulators paired along d (even/odd lanes), LDS.128 operands.
//
// smem (floats), 38,544 B total:
//   GEMM phase: hs[64][68] @0, w2s[72][68] @4352 (ends 9248)
//   epilogue:   exe_s[64][72] @0 (alias), un_s[64][72] @4608 (alias)
//   persistent: lut (648 x uint16, packed kk|u<<8) @9248, lutc[64] (uint32) @9572
// ---------------------------------------------------------------------------
__global__ __launch_bounds__(256, 4)
void fused_weight_gen(const float* __restrict__ W2,
                      const float* __restrict__ b2,
                      const float* __restrict__ unet,
                      float* __restrict__ out)
{
    __shared__ float sm[9636];
    float* hs    = sm;              // [64][68]
    float* w2s   = sm + 4352;       // [72][68]
    float* exe_s = sm;              // [64][72] (alias)
    float* un_s  = sm + 4608;       // [64][72] (alias)
    uint16_t* lut = (uint16_t*)(sm + 9248);   // 648 entries
    uint32_t* lutc = (uint32_t*)(sm + 9572);  // 64 entries

    const int tid    = threadIdx.x;
    const int ob     = blockIdx.x >> 3;
    const int ibg    = blockIdx.x & 7;
    const int ibbase = ibg * 8;
    const int base9  = (ob * 64 + ibbase) * 9;   // first of 72 contiguous W2 rows

    const int cg  = tid >> 3;   // 2 cells: cg*2, cg*2+1
    const int ibl = tid & 7;    // cols kk = ibl*9 + k

    // ---- fill persistent LUTs (synced by the first GEMM __syncthreads) ----
    for (int i = tid; i < 324; i += 256) {
        int e0 = 2 * i;
        int kk0 = e0 / 9, l0 = e0 - 9 * kk0;
        int u0  = (e0 / 81) * 9 + l0;
        int e1 = e0 + 1;
        int kk1 = e1 / 9, l1 = e1 - 9 * kk1;
        int u1  = (e1 / 81) * 9 + l1;
        uint32_t ent0 = (uint32_t)kk0 | ((uint32_t)u0 << 8);
        uint32_t ent1 = (uint32_t)kk1 | ((uint32_t)u1 << 8);
        ((uint32_t*)lut)[i] = ent0 | (ent1 << 16);
    }
    if (tid < 64) {
        int h = tid >> 3, kb = tid & 7;
        lutc[tid] = (uint32_t)(h * 2654208 + kb * 5184);  // h*64*512*81 + kb*64*81
    }

    unsigned long long acc0[9], acc1[9];
#pragma unroll
    for (int k = 0; k < 9; ++k) { acc0[k] = 0ull; acc1[k] = 0ull; }

    // ---- K loop: two halves of 64 d each ----
#pragma unroll 1
    for (int phase = 0; phase < 2; ++phase) {
        const int dbase = phase * 64;

        // hid half: 64 cells x 16 float4
        for (int idx = tid; idx < 1024; idx += 256) {
            int cell = idx >> 4, q = idx & 15;
            float4 v = *(const float4*)(g_hid + cell * 128 + dbase + 4 * q);
            *(float4*)(hs + cell * 68 + 4 * q) = v;
        }
        // W2 half: 72 rows x 16 float4 (rows contiguous in global)
        for (int idx = tid; idx < 1152; idx += 256) {
            int row = idx >> 4, q = idx & 15;
            float4 v = *(const float4*)(W2 + (size_t)(base9 + row) * 128 + dbase + 4 * q);
            *(float4*)(w2s + row * 68 + 4 * q) = v;
        }
        __syncthreads();

        const float* hp = hs + cg * 136;    // cg*2*68
        const float* wp = w2s + ibl * 612;  // ibl*9*68
#pragma unroll
        for (int dd = 0; dd < 64; dd += 4) {
            ulonglong2 h0 = *(const ulonglong2*)(hp + dd);
            ulonglong2 h1 = *(const ulonglong2*)(hp + 68 + dd);
#pragma unroll
            for (int k = 0; k < 9; ++k) {
                ulonglong2 w = *(const ulonglong2*)(wp + k * 68 + dd);
                FMA_F32X2(acc0[k], h0.x, w.x, acc0[k]);
                FMA_F32X2(acc0[k], h0.y, w.y, acc0[k]);
                FMA_F32X2(acc1[k], h1.x, w.x, acc1[k]);
                FMA_F32X2(acc1[k], h1.y, w.y, acc1[k]);
            }
        }
        __syncthreads();   // done reading this half before smem reuse
    }

    // ---- finalize exe into smem (aliases hs/w2s) ----
    {
        const int colbase = ibl * 9;
        const int c0 = cg * 2, c1 = c0 + 1;
#pragma unroll
        for (int k = 0; k < 9; ++k) {
            float bvk = b2[base9 + colbase + k];
            float2 p0 = *(float2*)&acc0[k];
            float2 p1 = *(float2*)&acc1[k];
            exe_s[c0 * 72 + colbase + k] = p0.x + p0.y + bvk;
            exe_s[c1 * 72 + colbase + k] = p1.x + p1.y + bvk;
        }
    }

    // stage unet: per cell 72 contiguous floats = 18 float4
    for (int idx = tid; idx < 1152; idx += 256) {
        int cell = idx / 18, q = idx - cell * 18;
        int h = cell >> 3, kb = cell & 7;
        size_t bu = ((size_t)(h * 64 + ob) * 512 + (size_t)(kb * 64 + ibbase)) * 9;
        float4 v = *(const float4*)(unet + bu + 4 * q);
        *(float4*)(un_s + cell * 72 + 4 * q) = v;
    }
    __syncthreads();

    // ---- epilogue: 10368 float4 per block, LUT-driven indexing ----
    const int outbase = ob * 41472 + ibbase * 81;
    for (int idx = tid; idx < 10368; idx += 256) {
        int cell = idx / 162;
        int r    = idx - cell * 162;
        int e    = r << 2;

        uint2 lv = *(const uint2*)(lut + e);   // 4 packed entries (kk | u<<8)
        const float* es = exe_s + cell * 72;
        const float* us = un_s  + cell * 72;

        uint32_t a = lv.x, b = lv.y;
        float v0 = es[a & 0xff]         * us[(a >> 8)  & 0xff];
        float v1 = es[(a >> 16) & 0xff] * us[(a >> 24)];
        float v2 = es[b & 0xff]         * us[(b >> 8)  & 0xff];
        float v3 = es[(b >> 16) & 0xff] * us[(b >> 24)];

        *(float4*)(out + outbase + lutc[cell] + e) = make_float4(v0, v1, v2, v3);
    }
}

// ---------------------------------------------------------------------------
extern "C" void kernel_launch(void* const* d_in, const int* in_sizes, int n_in,
                              void* d_out, int out_size)
{
    const float* z_all = (const float*)d_in[0];   // [64, 64]
    const float* W1    = (const float*)d_in[1];   // [128, 80]
    const float* b1    = (const float*)d_in[2];   // [128]
    const float* W2    = (const float*)d_in[3];   // [36864, 128]
    const float* b2    = (const float*)d_in[4];   // [36864]
    const float* unet  = (const float*)d_in[5];   // [512, 512, 9]
    const float* pde   = (const float*)d_in[6];   // [16]
    float* out = (float*)d_out;                   // [512, 512, 9, 9]

    hypernet_hid<<<64, 128>>>(z_all, W1, b1, pde);
    fused_weight_gen<<<512, 256>>>(W2, b2, unet, out);
}